// round 4
// baseline (speedup 1.0000x reference)
#include <cuda_runtime.h>
#include <math_constants.h>

// Problem constants
#define Bb 2
#define Hh 16
#define Ss 2048
#define Dd 64

// Tiling
#define TQ 128
#define TK 64
#define NT 256
#define KTILES (Ss / TK)        // 32

// smem strides (floats); all ≡ 4 (mod 32) -> conflict-free fragment loads
#define QS 132                  // q_hi/q_lo: [d][q]
#define KS 68                   // k/v tiles: [d][k] or [k][d]
#define PS 68                   // p tiles:   [q][k]

// smem layout (floats), sweep-1 view
#define OFF_QHI 0
#define OFF_QLO (64*QS)                 // 8448
#define OFF_KHI (2*64*QS)               // 16896
#define OFF_KLO (2*64*QS + 64*KS)       // 21248
// sweep-2 overlay
#define OFF_VHI 0
#define OFF_VLO (64*KS)                 // 4352
#define OFF_PHI (2*64*KS)               // 8704
#define OFF_PLO (2*64*KS + 128*PS)      // 17408
#define SMEM_FLOATS (2*64*KS + 2*128*PS)  // 26112 floats = 104448 B

// 1 -> mask elements are 4 bytes (int32/float32; masked iff word != 0)
// 0 -> mask elements are 1 byte (packed bools)
__device__ int g_mask_elem4;

__global__ void detect_mask_kernel(const unsigned int* __restrict__ mw)
{
    int has_bigbyte = 0, has_bigword = 0;
    for (int i = threadIdx.x; i < 4096; i += NT) {
        unsigned w = mw[i];
        unsigned b0 = w & 0xffu, b1 = (w >> 8) & 0xffu,
                 b2 = (w >> 16) & 0xffu, b3 = (w >> 24) & 0xffu;
        if (b0 > 1u || b1 > 1u || b2 > 1u || b3 > 1u) has_bigbyte = 1;
        if (w > 1u) has_bigword = 1;
    }
    has_bigbyte = __syncthreads_or(has_bigbyte);
    has_bigword = __syncthreads_or(has_bigword);
    if (threadIdx.x == 0)
        g_mask_elem4 = has_bigbyte ? 1 : (has_bigword ? 0 : 1);
}

__device__ __forceinline__ unsigned f2tf32(float x)
{
    unsigned r;
    asm("cvt.rna.tf32.f32 %0, %1;" : "=r"(r) : "f"(x));
    return r;
}

// x ~= hi + lo, both exactly representable in tf32
__device__ __forceinline__ void tf32_split(float x, float& hi, float& lo)
{
    hi = __uint_as_float(f2tf32(x));
    lo = __uint_as_float(f2tf32(x - hi));
}

__device__ __forceinline__ void mma8(float* c,
                                     unsigned a0, unsigned a1, unsigned a2, unsigned a3,
                                     unsigned b0, unsigned b1)
{
    asm volatile(
        "mma.sync.aligned.m16n8k8.row.col.f32.tf32.tf32.f32 "
        "{%0,%1,%2,%3}, {%4,%5,%6,%7}, {%8,%9}, {%0,%1,%2,%3};\n"
        : "+f"(c[0]), "+f"(c[1]), "+f"(c[2]), "+f"(c[3])
        : "r"(a0), "r"(a1), "r"(a2), "r"(a3), "r"(b0), "r"(b1));
}

__global__ __launch_bounds__(NT, 2)
void attn_mma_kernel(const float* __restrict__ Qg_,
                     const float* __restrict__ Kg_,
                     const float* __restrict__ Vg_,
                     const void* __restrict__ Mg_,
                     float* __restrict__ ctx_out,
                     float* __restrict__ att_out)
{
    extern __shared__ float sm[];
    const int tid  = threadIdx.x;
    const int lane = tid & 31;
    const int wid  = tid >> 5;          // 8 warps
    const int gid  = lane >> 2;         // 0..7
    const int tig  = lane & 3;          // 0..3
    const int q0w  = wid * 16;          // warp's 16 q rows (local)

    const int qt = blockIdx.x;
    const int bh = blockIdx.y;
    const int b  = bh >> 4;
    const int q0 = qt * TQ;
    const bool mask4 = (g_mask_elem4 != 0);

    const size_t head_off = (size_t)bh * Ss * Dd;
    const float* Qg = Qg_ + head_off + (size_t)q0 * Dd;
    const float* Kg = Kg_ + head_off;
    const float* Vg = Vg_ + head_off;
    const size_t mask_row0 = (size_t)b * Ss * Ss + (size_t)q0 * Ss;
    const unsigned char* Mg1 = (const unsigned char*)Mg_ + mask_row0;
    const unsigned int*  Mg4 = (const unsigned int*)Mg_ + mask_row0;
    float* att = att_out + (size_t)bh * Ss * Ss + (size_t)q0 * Ss;
    float* ctx = ctx_out + head_off + (size_t)q0 * Dd;

    const float scale = 0.125f;     // 1/sqrt(64)
    const float NEG = -1e9f;

    // ---- Load + tf32-split Q tile into [d][q] smem ----
    for (int idx = tid; idx < TQ * Dd; idx += NT) {
        int q = idx >> 6, d = idx & 63;
        float hi, lo;
        tf32_split(Qg[idx], hi, lo);
        sm[OFF_QHI + d * QS + q] = hi;
        sm[OFF_QLO + d * QS + q] = lo;
    }

    // per-thread online softmax state for rows r0 = q0w+gid and r1 = r0+8
    float m0 = -CUDART_INF_F, m1 = -CUDART_INF_F, l0 = 0.0f, l1 = 0.0f;
    const int r0 = q0w + gid;
    const int r1 = r0 + 8;

    // ================= Sweep 1: scores (raw, staged to gmem) + (m, l) ======
    for (int kt = 0; kt < KTILES; kt++) {
        __syncthreads();     // previous iter's fragment reads done
        // Load + split K tile into [d][k]
        for (int idx = tid; idx < TK * Dd; idx += NT) {
            int k = idx >> 6, d = idx & 63;
            float hi, lo;
            tf32_split(Kg[(size_t)kt * TK * Dd + idx], hi, lo);
            sm[OFF_KHI + d * KS + k] = hi;
            sm[OFF_KLO + d * KS + k] = lo;
        }
        __syncthreads();

        float acc[8][4];
#pragma unroll
        for (int n = 0; n < 8; n++)
#pragma unroll
            for (int j = 0; j < 4; j++) acc[n][j] = 0.0f;

#pragma unroll
        for (int ks = 0; ks < 8; ks++) {
            const int d0 = ks * 8 + tig;
            const int d4 = d0 + 4;
            unsigned ah0 = __float_as_uint(sm[OFF_QHI + d0 * QS + r0]);
            unsigned ah1 = __float_as_uint(sm[OFF_QHI + d0 * QS + r1]);
            unsigned ah2 = __float_as_uint(sm[OFF_QHI + d4 * QS + r0]);
            unsigned ah3 = __float_as_uint(sm[OFF_QHI + d4 * QS + r1]);
            unsigned al0 = __float_as_uint(sm[OFF_QLO + d0 * QS + r0]);
            unsigned al1 = __float_as_uint(sm[OFF_QLO + d0 * QS + r1]);
            unsigned al2 = __float_as_uint(sm[OFF_QLO + d4 * QS + r0]);
            unsigned al3 = __float_as_uint(sm[OFF_QLO + d4 * QS + r1]);
#pragma unroll
            for (int nb = 0; nb < 8; nb++) {
                unsigned bh0 = __float_as_uint(sm[OFF_KHI + d0 * KS + nb * 8 + gid]);
                unsigned bh1 = __float_as_uint(sm[OFF_KHI + d4 * KS + nb * 8 + gid]);
                unsigned bl0 = __float_as_uint(sm[OFF_KLO + d0 * KS + nb * 8 + gid]);
                unsigned bl1 = __float_as_uint(sm[OFF_KLO + d4 * KS + nb * 8 + gid]);
                mma8(acc[nb], ah0, ah1, ah2, ah3, bh0, bh1);
                mma8(acc[nb], ah0, ah1, ah2, ah3, bl0, bl1);
                mma8(acc[nb], al0, al1, al2, al3, bh0, bh1);
            }
        }

        // Epilogue: mask + scale, stage raw scores, online max/sum
#pragma unroll
        for (int nb = 0; nb < 8; nb++) {
            const int col = kt * TK + nb * 8 + 2 * tig;
            bool k00, k01, k10, k11;
            if (mask4) {
                uint2 w0 = *(const uint2*)(Mg4 + (size_t)r0 * Ss + col);
                uint2 w1 = *(const uint2*)(Mg4 + (size_t)r1 * Ss + col);
                k00 = w0.x != 0u; k01 = w0.y != 0u;
                k10 = w1.x != 0u; k11 = w1.y != 0u;
            } else {
                const unsigned char* p0 = Mg1 + (size_t)r0 * Ss + col;
                const unsigned char* p1 = Mg1 + (size_t)r1 * Ss + col;
                k00 = p0[0] != 0; k01 = p0[1] != 0;
                k10 = p1[0] != 0; k11 = p1[1] != 0;
            }
            float s00 = k00 ? NEG : acc[nb][0] * scale;
            float s01 = k01 ? NEG : acc[nb][1] * scale;
            float s10 = k10 ? NEG : acc[nb][2] * scale;
            float s11 = k11 ? NEG : acc[nb][3] * scale;
            *(float2*)(att + (size_t)r0 * Ss + col) = make_float2(s00, s01);
            *(float2*)(att + (size_t)r1 * Ss + col) = make_float2(s10, s11);

            float mx0 = fmaxf(s00, s01);
            float nm0 = fmaxf(m0, mx0);
            l0 = l0 * __expf(m0 - nm0) + __expf(s00 - nm0) + __expf(s01 - nm0);
            m0 = nm0;
            float mx1 = fmaxf(s10, s11);
            float nm1 = fmaxf(m1, mx1);
            l1 = l1 * __expf(m1 - nm1) + __expf(s10 - nm1) + __expf(s11 - nm1);
            m1 = nm1;
        }
    }

    // ---- Reduce (m, l) across the 4 lanes of each quad (same rows) ----
#pragma unroll
    for (int off = 1; off <= 2; off <<= 1) {
        float mo = __shfl_xor_sync(0xffffffffu, m0, off);
        float lo_ = __shfl_xor_sync(0xffffffffu, l0, off);
        float nm = fmaxf(m0, mo);
        l0 = l0 * __expf(m0 - nm) + lo_ * __expf(mo - nm);
        m0 = nm;
        mo  = __shfl_xor_sync(0xffffffffu, m1, off);
        lo_ = __shfl_xor_sync(0xffffffffu, l1, off);
        nm = fmaxf(m1, mo);
        l1 = l1 * __expf(m1 - nm) + lo_ * __expf(mo - nm);
        m1 = nm;
    }
    const float rl0 = 1.0f / l0;
    const float rl1 = 1.0f / l1;

    // ================= Sweep 2: normalize + P·V ============================
    float cacc[8][4];
#pragma unroll
    for (int n = 0; n < 8; n++)
#pragma unroll
        for (int j = 0; j < 4; j++) cacc[n][j] = 0.0f;

    for (int kt = 0; kt < KTILES; kt++) {
        __syncthreads();    // previous iter's fragment reads (and sweep-1 smem) done

        // Load + split V tile into [k][d]
        for (int idx = tid; idx < TK * Dd; idx += NT) {
            int k = idx >> 6, d = idx & 63;
            float hi, lo;
            tf32_split(Vg[(size_t)kt * TK * Dd + idx], hi, lo);
            sm[OFF_VHI + k * KS + d] = hi;
            sm[OFF_VLO + k * KS + d] = lo;
        }

        // Normalize my staged scores -> attention out + split into p smem
#pragma unroll
        for (int nb = 0; nb < 8; nb++) {
            const int colt = nb * 8 + 2 * tig;       // col within tile (0..63)
            const int col  = kt * TK + colt;
            float2 s0 = *(const float2*)(att + (size_t)r0 * Ss + col);
            float2 s1 = *(const float2*)(att + (size_t)r1 * Ss + col);
            float p00 = __expf(s0.x - m0) * rl0;
            float p01 = __expf(s0.y - m0) * rl0;
            float p10 = __expf(s1.x - m1) * rl1;
            float p11 = __expf(s1.y - m1) * rl1;
            *(float2*)(att + (size_t)r0 * Ss + col) = make_float2(p00, p01);
            *(float2*)(att + (size_t)r1 * Ss + col) = make_float2(p10, p11);

            float hi, lo;
            tf32_split(p00, hi, lo);
            sm[OFF_PHI + r0 * PS + colt]     = hi;  sm[OFF_PLO + r0 * PS + colt]     = lo;
            tf32_split(p01, hi, lo);
            sm[OFF_PHI + r0 * PS + colt + 1] = hi;  sm[OFF_PLO + r0 * PS + colt + 1] = lo;
            tf32_split(p10, hi, lo);
            sm[OFF_PHI + r1 * PS + colt]     = hi;  sm[OFF_PLO + r1 * PS + colt]     = lo;
            tf32_split(p11, hi, lo);
            sm[OFF_PHI + r1 * PS + colt + 1] = hi;  sm[OFF_PLO + r1 * PS + colt + 1] = lo;
        }
        __syncthreads();

        // ctx += P(16xTK) @ V(TKx64)
#pragma unroll
        for (int ks = 0; ks < 8; ks++) {
            const int k0 = ks * 8 + tig;
            const int k4 = k0 + 4;
            unsigned ah0 = __float_as_uint(sm[OFF_PHI + r0 * PS + k0]);
            unsigned ah1 = __float_as_uint(sm[OFF_PHI + r1 * PS + k0]);
            unsigned ah2 = __float_as_uint(sm[OFF_PHI + r0 * PS + k4]);
            unsigned ah3 = __float_as_uint(sm[OFF_PHI + r1 * PS + k4]);
            unsigned al0 = __float_as_uint(sm[OFF_PLO + r0 * PS + k0]);
            unsigned al1 = __float_as_uint(sm[OFF_PLO + r1 * PS + k0]);
            unsigned al2 = __float_as_uint(sm[OFF_PLO + r0 * PS + k4]);
            unsigned al3 = __float_as_uint(sm[OFF_PLO + r1 * PS + k4]);
#pragma unroll
            for (int nb = 0; nb < 8; nb++) {
                unsigned bh0 = __float_as_uint(sm[OFF_VHI + k0 * KS + nb * 8 + gid]);
                unsigned bh1 = __float_as_uint(sm[OFF_VHI + k4 * KS + nb * 8 + gid]);
                unsigned bl0 = __float_as_uint(sm[OFF_VLO + k0 * KS + nb * 8 + gid]);
                unsigned bl1 = __float_as_uint(sm[OFF_VLO + k4 * KS + nb * 8 + gid]);
                mma8(cacc[nb], ah0, ah1, ah2, ah3, bh0, bh1);
                mma8(cacc[nb], ah0, ah1, ah2, ah3, bl0, bl1);
                mma8(cacc[nb], al0, al1, al2, al3, bh0, bh1);
            }
        }
    }

    // ---- Write context ----
#pragma unroll
    for (int nb = 0; nb < 8; nb++) {
        const int col = nb * 8 + 2 * tig;
        *(float2*)(ctx + (size_t)r0 * Dd + col) = make_float2(cacc[nb][0], cacc[nb][1]);
        *(float2*)(ctx + (size_t)r1 * Dd + col) = make_float2(cacc[nb][2], cacc[nb][3]);
    }
}

extern "C" void kernel_launch(void* const* d_in, const int* in_sizes, int n_in,
                              void* d_out, int out_size)
{
    const float* Q = (const float*)d_in[0];
    const float* K = (const float*)d_in[1];
    const float* V = (const float*)d_in[2];
    const void*  M = d_in[3];
    // d_in[4] = dim_key (constant 64), unused

    float* out = (float*)d_out;
    float* ctx = out;                                   // [B,H,S,D]
    float* att = out + (size_t)Bb * Hh * Ss * Dd;       // [B,H,S,S]

    const size_t smem = SMEM_FLOATS * sizeof(float);    // 104448 B
    cudaFuncSetAttribute(attn_mma_kernel,
                         cudaFuncAttributeMaxDynamicSharedMemorySize, (int)smem);

    detect_mask_kernel<<<1, NT>>>((const unsigned int*)M);

    dim3 grid(Ss / TQ, Bb * Hh);                        // (16, 32) = 512 CTAs
    attn_mma_kernel<<<grid, NT, smem>>>(Q, K, V, M, ctx, att);
}